// round 2
// baseline (speedup 1.0000x reference)
#include <cuda_runtime.h>
#include <mma.h>
#include <cstdint>

using namespace nvcuda;

// Problem shape (fixed by the dataset)
static constexpr int Mtot = 8192;   // B*S
static constexpr int Ntot = 4096;   // OUT
static constexpr int Ktot = 4096;   // IN
static constexpr int RANK = 16;

// GEMM tiling
static constexpr int BM = 128;
static constexpr int BN = 128;
static constexpr int BK = 32;
static constexpr int LDT = 40;      // padded smem tile leading dim (floats)
static constexpr int LDC = 132;     // padded epilogue staging leading dim
static constexpr int TILE_F = BM * LDT;              // 5120 floats per tile
static constexpr int SMEM_FLOATS = 4 * TILE_F;       // 2 bufs x (A + B) = 20480
static constexpr int SMEM_BYTES = SMEM_FLOATS * 4;   // 81920 B

// Fused weight scratch: W' = W + down @ up   [OUT, IN] row-major
__device__ float g_w[(size_t)Ntot * Ktot];

// ---------------------------------------------------------------------------
// Kernel 1: fold the rank-16 LoRA update into the weight.
// One block per output row; 1024 threads x float4 covers IN=4096 exactly.
// HBM-bound: ~130 MB rw -> ~20-25 us. 'up' (256 KB) stays L2-resident.
// ---------------------------------------------------------------------------
__global__ void fuse_weight_kernel(const float* __restrict__ W,
                                   const float* __restrict__ down,
                                   const float* __restrict__ up) {
    const int o  = blockIdx.x;
    const int i4 = threadIdx.x;  // float4 index, 0..1023 -> covers 4096 floats

    float d[RANK];
#pragma unroll
    for (int r = 0; r < RANK; r++) d[r] = __ldg(&down[o * RANK + r]);

    float4 acc = reinterpret_cast<const float4*>(W + (size_t)o * Ktot)[i4];
#pragma unroll
    for (int r = 0; r < RANK; r++) {
        float4 u = reinterpret_cast<const float4*>(up + (size_t)r * Ktot)[i4];
        acc.x = fmaf(d[r], u.x, acc.x);
        acc.y = fmaf(d[r], u.y, acc.y);
        acc.z = fmaf(d[r], u.z, acc.z);
        acc.w = fmaf(d[r], u.w, acc.w);
    }
    reinterpret_cast<float4*>(g_w + (size_t)o * Ktot)[i4] = acc;
}

// ---------------------------------------------------------------------------
// Kernel 2: out = x @ W'^T + bias,  tf32 wmma, cp.async double buffering.
// CTA tile 128x128x32, 8 warps (2x4), warp tile 64x32 (4x2 of m16n16k8).
// ---------------------------------------------------------------------------
__device__ __forceinline__ void cp_async16(float* smem_dst, const float* gsrc) {
    uint32_t s = (uint32_t)__cvta_generic_to_shared(smem_dst);
    asm volatile("cp.async.cg.shared.global [%0], [%1], 16;\n" :: "r"(s), "l"(gsrc));
}

__device__ __forceinline__ void load_tile(float* aS, float* bS,
                                          const float* __restrict__ x,
                                          int bm, int bn, int k0, int tid) {
#pragma unroll
    for (int j = 0; j < 4; j++) {
        int idx = tid + j * 256;      // 0..1023
        int r   = idx >> 3;           // row 0..127
        int c4  = idx & 7;            // float4 col 0..7 (BK=32)
        cp_async16(aS + r * LDT + c4 * 4,
                   x + (size_t)(bm + r) * Ktot + k0 + c4 * 4);
        cp_async16(bS + r * LDT + c4 * 4,
                   g_w + (size_t)(bn + r) * Ktot + k0 + c4 * 4);
    }
}

__global__ __launch_bounds__(256, 2)
void lora_gemm_kernel(const float* __restrict__ x,
                      const float* __restrict__ bias,
                      float* __restrict__ out) {
    extern __shared__ float smem[];
    float* As0 = smem;
    float* Bs0 = smem + TILE_F;
    float* As1 = smem + 2 * TILE_F;
    float* Bs1 = smem + 3 * TILE_F;

    const int tid    = threadIdx.x;
    const int wid    = tid >> 5;
    const int warp_m = wid & 1;   // 0..1 -> 64 rows each
    const int warp_n = wid >> 1;  // 0..3 -> 32 cols each
    const int bm = blockIdx.y * BM;
    const int bn = blockIdx.x * BN;

    wmma::fragment<wmma::accumulator, 16, 16, 8, float> c[4][2];
#pragma unroll
    for (int mf = 0; mf < 4; mf++)
#pragma unroll
        for (int nf = 0; nf < 2; nf++)
            wmma::fill_fragment(c[mf][nf], 0.0f);

    constexpr int KT = Ktot / BK;  // 128 iterations

    // Prologue: stage tile 0
    load_tile(As0, Bs0, x, bm, bn, 0, tid);
    asm volatile("cp.async.commit_group;\n");

    for (int kt = 0; kt < KT; kt++) {
        float* aS = (kt & 1) ? As1 : As0;
        float* bS = (kt & 1) ? Bs1 : Bs0;

        if (kt + 1 < KT) {
            float* aN = (kt & 1) ? As0 : As1;
            float* bN = (kt & 1) ? Bs0 : Bs1;
            load_tile(aN, bN, x, bm, bn, (kt + 1) * BK, tid);
            asm volatile("cp.async.commit_group;\n");
            asm volatile("cp.async.wait_group 1;\n");  // tile kt resident
        } else {
            asm volatile("cp.async.wait_group 0;\n");
        }
        __syncthreads();

#pragma unroll
        for (int ks = 0; ks < 4; ks++) {
            wmma::fragment<wmma::matrix_a, 16, 16, 8, wmma::precision::tf32,
                           wmma::row_major> a[4];
            wmma::fragment<wmma::matrix_b, 16, 16, 8, wmma::precision::tf32,
                           wmma::col_major> b[2];
#pragma unroll
            for (int mf = 0; mf < 4; mf++) {
                wmma::load_matrix_sync(
                    a[mf], aS + (warp_m * 64 + mf * 16) * LDT + ks * 8, LDT);
#pragma unroll
                for (int t = 0; t < a[mf].num_elements; t++)
                    a[mf].x[t] = wmma::__float_to_tf32(a[mf].x[t]);
            }
#pragma unroll
            for (int nf = 0; nf < 2; nf++) {
                wmma::load_matrix_sync(
                    b[nf], bS + (warp_n * 32 + nf * 16) * LDT + ks * 8, LDT);
#pragma unroll
                for (int t = 0; t < b[nf].num_elements; t++)
                    b[nf].x[t] = wmma::__float_to_tf32(b[nf].x[t]);
            }
#pragma unroll
            for (int mf = 0; mf < 4; mf++)
#pragma unroll
                for (int nf = 0; nf < 2; nf++)
                    wmma::mma_sync(c[mf][nf], a[mf], b[nf], c[mf][nf]);
        }
        __syncthreads();  // protects buffer reuse by the NEXT prefetch
    }

    // Epilogue: stage C through smem (reuse tile buffers), fuse bias,
    // vectorized coalesced global store.
    float* Cs = smem;  // needs 128*132 = 16896 floats <= 20480 available
    const int cm = warp_m * 64;
    const int cn = warp_n * 32;
#pragma unroll
    for (int mf = 0; mf < 4; mf++)
#pragma unroll
        for (int nf = 0; nf < 2; nf++)
            wmma::store_matrix_sync(Cs + (cm + mf * 16) * LDC + cn + nf * 16,
                                    c[mf][nf], LDC, wmma::mem_row_major);
    __syncthreads();

#pragma unroll
    for (int j = 0; j < 16; j++) {
        int idx = tid + j * 256;   // 0..4095
        int r   = idx >> 5;        // row 0..127
        int c4  = idx & 31;        // float4 col 0..31
        float4 v  = *reinterpret_cast<float4*>(Cs + r * LDC + c4 * 4);
        float4 bv = *reinterpret_cast<const float4*>(bias + bn + c4 * 4);
        v.x += bv.x; v.y += bv.y; v.z += bv.z; v.w += bv.w;
        *reinterpret_cast<float4*>(out + (size_t)(bm + r) * Ntot + bn + c4 * 4) = v;
    }
}

// ---------------------------------------------------------------------------
// Launch
// ---------------------------------------------------------------------------
extern "C" void kernel_launch(void* const* d_in, const int* in_sizes, int n_in,
                              void* d_out, int out_size) {
    const float* x    = (const float*)d_in[0];  // [8192, 4096]
    const float* W    = (const float*)d_in[1];  // [4096, 4096]
    const float* bias = (const float*)d_in[2];  // [4096]
    const float* down = (const float*)d_in[3];  // [4096, 16]
    const float* up   = (const float*)d_in[4];  // [16, 4096]
    float* out = (float*)d_out;                 // [8192, 4096]

    (void)in_sizes; (void)n_in; (void)out_size;

    // Idempotent host-side config (no stream work, capture-safe).
    cudaFuncSetAttribute(lora_gemm_kernel,
                         cudaFuncAttributeMaxDynamicSharedMemorySize, SMEM_BYTES);

    fuse_weight_kernel<<<Ntot, 1024>>>(W, down, up);

    dim3 grid(Ntot / BN, Mtot / BM);  // (32, 64)
    lora_gemm_kernel<<<grid, 256, SMEM_BYTES>>>(x, bias, out);
}

// round 4
// speedup vs baseline: 5.4001x; 5.4001x over previous
#include <cuda_runtime.h>
#include <cuda.h>
#include <cuda_fp16.h>
#include <cstdint>
#include <cstddef>

// ---------------------------------------------------------------------------
// Problem shape (fixed by dataset)
// ---------------------------------------------------------------------------
static constexpr int Mtot = 8192;   // B*S
static constexpr int Ntot = 4096;   // OUT
static constexpr int Ktot = 4096;   // IN
static constexpr int RANK = 16;

// GEMM tiling
static constexpr int BM = 256;              // CTA M tile
static constexpr int BN = 128;              // CTA N tile
static constexpr int BK = 64;               // 64 fp16 = 128B row = SW128 atom
static constexpr int KSTEPS = Ktot / BK;    // 64
static constexpr int STAGES = 4;

static constexpr int A_BYTES = BM * BK * 2;            // 32 KB
static constexpr int B_BYTES = BN * BK * 2;            // 16 KB
static constexpr int STAGE_BYTES = A_BYTES + B_BYTES;  // 48 KB
static constexpr int SMEM_ALLOC = 2048 + STAGES * STAGE_BYTES;  // 198656 B

// fp16 scratch: W' = W + down@up, and x converted
__device__ __align__(1024) __half g_wh[(size_t)Ntot * Ktot];
__device__ __align__(1024) __half g_xh[(size_t)Mtot * Ktot];

// ---------------------------------------------------------------------------
// PTX helpers (all non-'a' instructions: sm_90 baseline TMA + sm_80 mma)
// ---------------------------------------------------------------------------
__device__ __forceinline__ uint32_t s2u(const void* p) {
    uint32_t a;
    asm("{ .reg .u64 t; cvta.to.shared.u64 t, %1; cvt.u32.u64 %0, t; }"
        : "=r"(a) : "l"(p));
    return a;
}

#define MBAR_INIT(addr, cnt) \
    asm volatile("mbarrier.init.shared.b64 [%0], %1;" :: "r"(addr), "r"(cnt) : "memory")

#define MBAR_EXPECT_TX(addr, bytes) \
    asm volatile("mbarrier.arrive.expect_tx.shared.b64 _, [%0], %1;" \
                 :: "r"(addr), "r"(bytes) : "memory")

#define MBAR_ARRIVE(addr) \
    asm volatile("mbarrier.arrive.shared.b64 _, [%0];" :: "r"(addr) : "memory")

#define MBAR_WAIT(addr, parity) do {                                          \
    uint32_t _mb = (addr); uint32_t _ph = (parity); uint32_t _done;           \
    asm volatile("{\n\t.reg .pred p;\n\t"                                     \
        "mbarrier.try_wait.parity.acquire.cta.shared::cta.b64 p, [%1], %2;\n\t" \
        "selp.b32 %0, 1, 0, p;\n\t}"                                          \
        : "=r"(_done) : "r"(_mb), "r"(_ph) : "memory");                       \
    if (!_done) {                                                             \
        asm volatile("{\n\t.reg .pred P1;\n\t"                                \
            "WL_%=:\n\t"                                                      \
            "mbarrier.try_wait.parity.acquire.cta.shared::cta.b64 P1, [%0], %1, 0x989680;\n\t" \
            "@P1 bra.uni WD_%=;\n\t"                                          \
            "bra.uni WL_%=;\n\t"                                              \
            "WD_%=:\n\t}" :: "r"(_mb), "r"(_ph) : "memory");                  \
    }                                                                         \
} while (0)

#define TMA2D(dst, map, cx, cy, mbar)                                         \
    asm volatile("cp.async.bulk.tensor.2d.shared::cta.global.tile"            \
                 ".mbarrier::complete_tx::bytes [%0], [%1, {%2, %3}], [%4];"  \
                 :: "r"(dst), "l"(map), "r"(cx), "r"(cy), "r"(mbar) : "memory")

__device__ __forceinline__ void ldsm4(uint32_t* r, uint32_t addr) {
    asm volatile("ldmatrix.sync.aligned.m8n8.x4.shared.b16 {%0,%1,%2,%3}, [%4];"
                 : "=r"(r[0]), "=r"(r[1]), "=r"(r[2]), "=r"(r[3]) : "r"(addr));
}

__device__ __forceinline__ void mma16816(float* c, const uint32_t* a, const uint32_t* b) {
    asm volatile(
        "mma.sync.aligned.m16n8k16.row.col.f32.f16.f16.f32 "
        "{%0,%1,%2,%3}, {%4,%5,%6,%7}, {%8,%9}, {%0,%1,%2,%3};"
        : "+f"(c[0]), "+f"(c[1]), "+f"(c[2]), "+f"(c[3])
        : "r"(a[0]), "r"(a[1]), "r"(a[2]), "r"(a[3]), "r"(b[0]), "r"(b[1]));
}

// ---------------------------------------------------------------------------
// Kernel 1: W' = W + down @ up, cast to fp16.  One block per output row.
// ---------------------------------------------------------------------------
__global__ void fuse_weight_kernel(const float* __restrict__ W,
                                   const float* __restrict__ down,
                                   const float* __restrict__ up) {
    const int o  = blockIdx.x;
    const int i4 = threadIdx.x;  // 0..1023 float4s -> 4096 floats

    float d[RANK];
#pragma unroll
    for (int r = 0; r < RANK; r++) d[r] = __ldg(&down[o * RANK + r]);

    float4 acc = reinterpret_cast<const float4*>(W + (size_t)o * Ktot)[i4];
#pragma unroll
    for (int r = 0; r < RANK; r++) {
        float4 u = reinterpret_cast<const float4*>(up + (size_t)r * Ktot)[i4];
        acc.x = fmaf(d[r], u.x, acc.x);
        acc.y = fmaf(d[r], u.y, acc.y);
        acc.z = fmaf(d[r], u.z, acc.z);
        acc.w = fmaf(d[r], u.w, acc.w);
    }
    __half2 h01 = __floats2half2_rn(acc.x, acc.y);
    __half2 h23 = __floats2half2_rn(acc.z, acc.w);
    uint2 pk;
    pk.x = *reinterpret_cast<const uint32_t*>(&h01);
    pk.y = *reinterpret_cast<const uint32_t*>(&h23);
    *reinterpret_cast<uint2*>(g_wh + (size_t)o * Ktot + i4 * 4) = pk;
}

// ---------------------------------------------------------------------------
// Kernel 2: x -> fp16
// ---------------------------------------------------------------------------
__global__ void convert_x_kernel(const float* __restrict__ x) {
    const size_t idx = (size_t)blockIdx.x * blockDim.x + threadIdx.x;  // float4 idx
    float4 v = reinterpret_cast<const float4*>(x)[idx];
    __half2 h01 = __floats2half2_rn(v.x, v.y);
    __half2 h23 = __floats2half2_rn(v.z, v.w);
    uint2 pk;
    pk.x = *reinterpret_cast<const uint32_t*>(&h01);
    pk.y = *reinterpret_cast<const uint32_t*>(&h23);
    *reinterpret_cast<uint2*>(g_xh + idx * 4) = pk;
}

// ---------------------------------------------------------------------------
// Kernel 3: out = x @ W'^T + bias.  fp16 HMMA, TMA 4-stage pipeline.
// CTA 256x128x64, 512 threads (16 warps, 4x4), warp tile 64x32.
// ---------------------------------------------------------------------------
__global__ __launch_bounds__(512, 1)
void lora_gemm_hmma(const __grid_constant__ CUtensorMap tmap_x,
                    const __grid_constant__ CUtensorMap tmap_w,
                    const float* __restrict__ bias,
                    float* __restrict__ out)
{
    extern __shared__ char smraw[];
    const uint32_t raw  = s2u(smraw);
    const uint32_t base = (raw + 1023u) & ~1023u;

    const uint32_t mb_full  = base;        // 4 x 8B
    const uint32_t mb_empty = base + 64;   // 4 x 8B
    const uint32_t tiles    = base + 1024;

    const int tid  = threadIdx.x;
    const int wid  = tid >> 5;
    const int lane = tid & 31;
    const int bm = blockIdx.y * BM;
    const int bn = blockIdx.x * BN;
    const int warp_m = wid >> 2;   // 0..3 -> 64 rows
    const int warp_n = wid & 3;    // 0..3 -> 32 cols

    if (tid == 0) {
        for (int s = 0; s < STAGES; s++) {
            MBAR_INIT(mb_full  + 8 * s, 1);
            MBAR_INIT(mb_empty + 8 * s, 512);
        }
    }
    __syncthreads();

    // Prologue: stage 0..STAGES-2
    if (tid == 0) {
#pragma unroll
        for (int s = 0; s < STAGES - 1; s++) {
            MBAR_EXPECT_TX(mb_full + 8 * s, (uint32_t)STAGE_BYTES);
            const uint32_t sa = tiles + s * STAGE_BYTES;
            TMA2D(sa,           &tmap_x, s * BK, bm, mb_full + 8 * s);
            TMA2D(sa + A_BYTES, &tmap_w, s * BK, bn, mb_full + 8 * s);
        }
    }

    float c[4][4][4];
#pragma unroll
    for (int i = 0; i < 4; i++)
#pragma unroll
        for (int j = 0; j < 4; j++)
#pragma unroll
            for (int k = 0; k < 4; k++) c[i][j][k] = 0.0f;

    // Per-lane smem addressing (SW128: XOR const = (row&7)<<4, rows are 128B)
    const int lr16 = lane & 15;
    const int ahi  = (lane >> 4) << 4;            // A col byte offset: 0 / 16
    uint32_t a_off[4], a_xor[4];
#pragma unroll
    for (int mi = 0; mi < 4; mi++) {
        const int r = warp_m * 64 + mi * 16 + lr16;
        a_off[mi] = (uint32_t)r * 128;
        a_xor[mi] = (uint32_t)((r & 7) << 4);
    }
    const int brlo = (lane & 7) + ((lane >> 4) << 3);  // B row-in-16
    const int bhi  = ((lane >> 3) & 1) << 4;           // B col byte: 0 / 16
    uint32_t b_off[2], b_xor[2];
#pragma unroll
    for (int nj = 0; nj < 2; nj++) {
        const int r = warp_n * 32 + nj * 16 + brlo;
        b_off[nj] = (uint32_t)r * 128;
        b_xor[nj] = (uint32_t)((r & 7) << 4);
    }

    int slot = 0, phase = 0;
    for (int s = 0; s < KSTEPS; s++) {
        if (tid == 0 && s + STAGES - 1 < KSTEPS) {
            const int p  = s + STAGES - 1;
            const int ps = p & (STAGES - 1);
            if (p >= STAGES) MBAR_WAIT(mb_empty + 8 * ps, ((p >> 2) - 1) & 1);
            MBAR_EXPECT_TX(mb_full + 8 * ps, (uint32_t)STAGE_BYTES);
            const uint32_t sa = tiles + ps * STAGE_BYTES;
            TMA2D(sa,           &tmap_x, p * BK, bm, mb_full + 8 * ps);
            TMA2D(sa + A_BYTES, &tmap_w, p * BK, bn, mb_full + 8 * ps);
        }

        MBAR_WAIT(mb_full + 8 * slot, phase);
        const uint32_t aT = tiles + slot * STAGE_BYTES;
        const uint32_t bT = aT + A_BYTES;

#pragma unroll
        for (int ks = 0; ks < 4; ks++) {
            uint32_t a[4][4], b[2][4];
            const uint32_t acol = (uint32_t)(ks * 32 + ahi);
            const uint32_t bcol = (uint32_t)(ks * 32 + bhi);
#pragma unroll
            for (int mi = 0; mi < 4; mi++)
                ldsm4(a[mi], aT + a_off[mi] + (acol ^ a_xor[mi]));
#pragma unroll
            for (int nj = 0; nj < 2; nj++)
                ldsm4(b[nj], bT + b_off[nj] + (bcol ^ b_xor[nj]));
#pragma unroll
            for (int mi = 0; mi < 4; mi++)
#pragma unroll
                for (int nj = 0; nj < 4; nj++)
                    mma16816(c[mi][nj], a[mi], &b[nj >> 1][(nj & 1) * 2]);
        }

        MBAR_ARRIVE(mb_empty + 8 * slot);
        if (++slot == STAGES) { slot = 0; phase ^= 1; }
    }

    // Epilogue: direct register -> global, bias fused. 8B stores, full sectors.
    const int gid = lane >> 2;
    const int qid = lane & 3;
#pragma unroll
    for (int nj = 0; nj < 4; nj++) {
        const int col = bn + warp_n * 32 + nj * 8 + qid * 2;
        const float b0 = __ldg(bias + col);
        const float b1 = __ldg(bias + col + 1);
#pragma unroll
        for (int mi = 0; mi < 4; mi++) {
            const int row = bm + warp_m * 64 + mi * 16 + gid;
            float2 v0 = make_float2(c[mi][nj][0] + b0, c[mi][nj][1] + b1);
            float2 v1 = make_float2(c[mi][nj][2] + b0, c[mi][nj][3] + b1);
            *reinterpret_cast<float2*>(out + (size_t)row * Ntot + col)       = v0;
            *reinterpret_cast<float2*>(out + (size_t)(row + 8) * Ntot + col) = v1;
        }
    }
}

// ---------------------------------------------------------------------------
// Host launch
// ---------------------------------------------------------------------------
typedef CUresult (*EncodeTiledFn)(
    CUtensorMap*, CUtensorMapDataType, cuuint32_t, void*,
    const cuuint64_t*, const cuuint64_t*, const cuuint32_t*, const cuuint32_t*,
    CUtensorMapInterleave, CUtensorMapSwizzle, CUtensorMapL2promotion,
    CUtensorMapFloatOOBfill);

extern "C" void kernel_launch(void* const* d_in, const int* in_sizes, int n_in,
                              void* d_out, int out_size) {
    const float* x    = (const float*)d_in[0];  // [8192, 4096]
    const float* W    = (const float*)d_in[1];  // [4096, 4096]
    const float* bias = (const float*)d_in[2];  // [4096]
    const float* down = (const float*)d_in[3];  // [4096, 16]
    const float* up   = (const float*)d_in[4];  // [16, 4096]
    float* out = (float*)d_out;                 // [8192, 4096]
    (void)in_sizes; (void)n_in; (void)out_size;

    static EncodeTiledFn enc = nullptr;
    if (!enc) {
        void* p = nullptr;
        cudaDriverEntryPointQueryResult qr;
        cudaGetDriverEntryPointByVersion("cuTensorMapEncodeTiled", &p, 12000,
                                         cudaEnableDefault, &qr);
        enc = (EncodeTiledFn)p;
    }
    void* xh_ptr = nullptr, *wh_ptr = nullptr;
    cudaGetSymbolAddress(&xh_ptr, g_xh);
    cudaGetSymbolAddress(&wh_ptr, g_wh);

    CUtensorMap mx, mw;
    {
        cuuint64_t dims[2]    = {(cuuint64_t)Ktot, (cuuint64_t)Mtot};
        cuuint64_t strides[1] = {(cuuint64_t)Ktot * 2};
        cuuint32_t box[2]     = {(cuuint32_t)BK, (cuuint32_t)BM};
        cuuint32_t es[2]      = {1, 1};
        enc(&mx, CU_TENSOR_MAP_DATA_TYPE_FLOAT16, 2, xh_ptr,
            dims, strides, box, es,
            CU_TENSOR_MAP_INTERLEAVE_NONE, CU_TENSOR_MAP_SWIZZLE_128B,
            CU_TENSOR_MAP_L2_PROMOTION_L2_128B, CU_TENSOR_MAP_FLOAT_OOB_FILL_NONE);

        dims[1] = (cuuint64_t)Ntot;
        box[1]  = (cuuint32_t)BN;
        enc(&mw, CU_TENSOR_MAP_DATA_TYPE_FLOAT16, 2, wh_ptr,
            dims, strides, box, es,
            CU_TENSOR_MAP_INTERLEAVE_NONE, CU_TENSOR_MAP_SWIZZLE_128B,
            CU_TENSOR_MAP_L2_PROMOTION_L2_128B, CU_TENSOR_MAP_FLOAT_OOB_FILL_NONE);
    }

    cudaFuncSetAttribute(lora_gemm_hmma,
                         cudaFuncAttributeMaxDynamicSharedMemorySize, SMEM_ALLOC);

    fuse_weight_kernel<<<Ntot, 1024>>>(W, down, up);
    convert_x_kernel<<<(Mtot * Ktot / 4) / 1024, 1024>>>(x);

    dim3 grid(Ntot / BN, Mtot / BM);  // (32, 32) = 1024 CTAs
    lora_gemm_hmma<<<grid, 512, SMEM_ALLOC>>>(mx, mw, bias, out);
}

// round 5
// speedup vs baseline: 5.4954x; 1.0176x over previous
#include <cuda_runtime.h>
#include <cuda.h>
#include <cuda_fp16.h>
#include <cstdint>
#include <cstddef>

// ---------------------------------------------------------------------------
// Problem shape (fixed by dataset)
// ---------------------------------------------------------------------------
static constexpr int Mtot = 8192;   // B*S
static constexpr int Ntot = 4096;   // OUT
static constexpr int Ktot = 4096;   // IN
static constexpr int RANK = 16;

// GEMM tiling
static constexpr int BM = 256;              // CTA M tile
static constexpr int BN = 128;              // CTA N tile
static constexpr int BK = 64;               // 64 fp16 = 128B row = SW128 atom
static constexpr int KSTEPS = Ktot / BK;    // 64
static constexpr int STAGES = 4;

static constexpr int A_BYTES = BM * BK * 2;            // 32 KB
static constexpr int B_BYTES = BN * BK * 2;            // 16 KB
static constexpr int STAGE_BYTES = A_BYTES + B_BYTES;  // 48 KB
static constexpr int SMEM_ALLOC = 2048 + STAGES * STAGE_BYTES;  // 198656 B

// fp16 scratch: W' = W + down@up, and x converted
__device__ __align__(1024) __half g_wh[(size_t)Ntot * Ktot];
__device__ __align__(1024) __half g_xh[(size_t)Mtot * Ktot];

// ---------------------------------------------------------------------------
// PTX helpers (all non-'a' instructions: sm_90 baseline TMA + sm_80 mma)
// ---------------------------------------------------------------------------
__device__ __forceinline__ uint32_t s2u(const void* p) {
    uint32_t a;
    asm("{ .reg .u64 t; cvta.to.shared.u64 t, %1; cvt.u32.u64 %0, t; }"
        : "=r"(a) : "l"(p));
    return a;
}

#define MBAR_INIT(addr, cnt) \
    asm volatile("mbarrier.init.shared.b64 [%0], %1;" :: "r"(addr), "r"(cnt) : "memory")

#define MBAR_EXPECT_TX(addr, bytes) \
    asm volatile("mbarrier.arrive.expect_tx.shared.b64 _, [%0], %1;" \
                 :: "r"(addr), "r"(bytes) : "memory")

#define MBAR_ARRIVE(addr) \
    asm volatile("mbarrier.arrive.shared.b64 _, [%0];" :: "r"(addr) : "memory")

#define MBAR_WAIT(addr, parity) do {                                          \
    uint32_t _mb = (addr); uint32_t _ph = (parity); uint32_t _done;           \
    asm volatile("{\n\t.reg .pred p;\n\t"                                     \
        "mbarrier.try_wait.parity.acquire.cta.shared::cta.b64 p, [%1], %2;\n\t" \
        "selp.b32 %0, 1, 0, p;\n\t}"                                          \
        : "=r"(_done) : "r"(_mb), "r"(_ph) : "memory");                       \
    if (!_done) {                                                             \
        asm volatile("{\n\t.reg .pred P1;\n\t"                                \
            "WL_%=:\n\t"                                                      \
            "mbarrier.try_wait.parity.acquire.cta.shared::cta.b64 P1, [%0], %1, 0x989680;\n\t" \
            "@P1 bra.uni WD_%=;\n\t"                                          \
            "bra.uni WL_%=;\n\t"                                              \
            "WD_%=:\n\t}" :: "r"(_mb), "r"(_ph) : "memory");                  \
    }                                                                         \
} while (0)

#define TMA2D(dst, map, cx, cy, mbar)                                         \
    asm volatile("cp.async.bulk.tensor.2d.shared::cta.global.tile"            \
                 ".mbarrier::complete_tx::bytes [%0], [%1, {%2, %3}], [%4];"  \
                 :: "r"(dst), "l"(map), "r"(cx), "r"(cy), "r"(mbar) : "memory")

__device__ __forceinline__ void ldsm4(uint32_t* r, uint32_t addr) {
    asm volatile("ldmatrix.sync.aligned.m8n8.x4.shared.b16 {%0,%1,%2,%3}, [%4];"
                 : "=r"(r[0]), "=r"(r[1]), "=r"(r[2]), "=r"(r[3]) : "r"(addr));
}

__device__ __forceinline__ void mma16816(float* c, const uint32_t* a, const uint32_t* b) {
    asm volatile(
        "mma.sync.aligned.m16n8k16.row.col.f32.f16.f16.f32 "
        "{%0,%1,%2,%3}, {%4,%5,%6,%7}, {%8,%9}, {%0,%1,%2,%3};"
        : "+f"(c[0]), "+f"(c[1]), "+f"(c[2]), "+f"(c[3])
        : "r"(a[0]), "r"(a[1]), "r"(a[2]), "r"(a[3]), "r"(b[0]), "r"(b[1]));
}

__device__ __forceinline__ uint2 pack_h4(float a, float b, float cc, float d) {
    __half2 h01 = __floats2half2_rn(a, b);
    __half2 h23 = __floats2half2_rn(cc, d);
    uint2 pk;
    pk.x = *reinterpret_cast<const uint32_t*>(&h01);
    pk.y = *reinterpret_cast<const uint32_t*>(&h23);
    return pk;
}

// ---------------------------------------------------------------------------
// Kernel 1 (merged): blocks [0, Ntot) fold W' = W + down@up -> fp16;
// blocks [Ntot, Ntot + XBLOCKS) convert x -> fp16 (2 float4s per thread).
// Running both halves in one grid overlaps the two memory streams.
// ---------------------------------------------------------------------------
static constexpr int XBLOCKS = 2048;  // (Mtot*Ktot/4) / (1024 thr * 4 f4/thr)

__global__ __launch_bounds__(1024, 1)
void prep_kernel(const float* __restrict__ W,
                 const float* __restrict__ down,
                 const float* __restrict__ up,
                 const float* __restrict__ x) {
    if (blockIdx.x < (unsigned)Ntot) {
        const int o  = blockIdx.x;
        const int i4 = threadIdx.x;  // 0..1023 float4s -> 4096 floats

        float d[RANK];
#pragma unroll
        for (int r = 0; r < RANK; r++) d[r] = __ldg(&down[o * RANK + r]);

        float4 acc = reinterpret_cast<const float4*>(W + (size_t)o * Ktot)[i4];
#pragma unroll
        for (int r = 0; r < RANK; r++) {
            float4 u = reinterpret_cast<const float4*>(up + (size_t)r * Ktot)[i4];
            acc.x = fmaf(d[r], u.x, acc.x);
            acc.y = fmaf(d[r], u.y, acc.y);
            acc.z = fmaf(d[r], u.z, acc.z);
            acc.w = fmaf(d[r], u.w, acc.w);
        }
        *reinterpret_cast<uint2*>(g_wh + (size_t)o * Ktot + (size_t)i4 * 4) =
            pack_h4(acc.x, acc.y, acc.z, acc.w);
    } else {
        // x conversion: 8M float4s over XBLOCKS blocks, 4 per thread
        const size_t blk = blockIdx.x - Ntot;
        size_t idx = (blk * 1024 + threadIdx.x) * 4;   // float4 index
        float4 v[4];
#pragma unroll
        for (int j = 0; j < 4; j++)
            v[j] = reinterpret_cast<const float4*>(x)[idx + j];
        uint2 pk[4];
#pragma unroll
        for (int j = 0; j < 4; j++)
            pk[j] = pack_h4(v[j].x, v[j].y, v[j].z, v[j].w);
#pragma unroll
        for (int j = 0; j < 4; j++)
            *reinterpret_cast<uint2*>(g_xh + (idx + j) * 4) = pk[j];
    }
}

// ---------------------------------------------------------------------------
// Kernel 2: out = x @ W'^T + bias.  fp16 HMMA, TMA 4-stage pipeline.
// CTA 256x128x64, 512 threads (16 warps, 4x4), warp tile 64x32.
// ---------------------------------------------------------------------------
__global__ __launch_bounds__(512, 1)
void lora_gemm_hmma(const __grid_constant__ CUtensorMap tmap_x,
                    const __grid_constant__ CUtensorMap tmap_w,
                    const float* __restrict__ bias,
                    float* __restrict__ out)
{
    extern __shared__ char smraw[];
    const uint32_t raw  = s2u(smraw);
    const uint32_t base = (raw + 1023u) & ~1023u;

    const uint32_t mb_full  = base;        // 4 x 8B
    const uint32_t mb_empty = base + 64;   // 4 x 8B
    const uint32_t tiles    = base + 1024;

    const int tid  = threadIdx.x;
    const int wid  = tid >> 5;
    const int lane = tid & 31;
    const int bm = blockIdx.y * BM;
    const int bn = blockIdx.x * BN;
    const int warp_m = wid >> 2;   // 0..3 -> 64 rows
    const int warp_n = wid & 3;    // 0..3 -> 32 cols

    if (tid == 0) {
        for (int s = 0; s < STAGES; s++) {
            MBAR_INIT(mb_full  + 8 * s, 1);
            MBAR_INIT(mb_empty + 8 * s, 16);   // one arrive per warp
        }
    }
    __syncthreads();

    // Prologue: stage 0..STAGES-2
    if (tid == 0) {
#pragma unroll
        for (int s = 0; s < STAGES - 1; s++) {
            MBAR_EXPECT_TX(mb_full + 8 * s, (uint32_t)STAGE_BYTES);
            const uint32_t sa = tiles + s * STAGE_BYTES;
            TMA2D(sa,           &tmap_x, s * BK, bm, mb_full + 8 * s);
            TMA2D(sa + A_BYTES, &tmap_w, s * BK, bn, mb_full + 8 * s);
        }
    }

    float c[4][4][4];
#pragma unroll
    for (int i = 0; i < 4; i++)
#pragma unroll
        for (int j = 0; j < 4; j++)
#pragma unroll
            for (int k = 0; k < 4; k++) c[i][j][k] = 0.0f;

    // Per-lane smem addressing (SW128: XOR const = (row&7)<<4, rows are 128B)
    const int lr16 = lane & 15;
    const int ahi  = (lane >> 4) << 4;            // A col byte offset: 0 / 16
    uint32_t a_off[4], a_xor[4];
#pragma unroll
    for (int mi = 0; mi < 4; mi++) {
        const int r = warp_m * 64 + mi * 16 + lr16;
        a_off[mi] = (uint32_t)r * 128;
        a_xor[mi] = (uint32_t)((r & 7) << 4);
    }
    const int brlo = (lane & 7) + ((lane >> 4) << 3);  // B row-in-16
    const int bhi  = ((lane >> 3) & 1) << 4;           // B col byte: 0 / 16
    uint32_t b_off[2], b_xor[2];
#pragma unroll
    for (int nj = 0; nj < 2; nj++) {
        const int r = warp_n * 32 + nj * 16 + brlo;
        b_off[nj] = (uint32_t)r * 128;
        b_xor[nj] = (uint32_t)((r & 7) << 4);
    }

    int slot = 0, phase = 0;
    for (int s = 0; s < KSTEPS; s++) {
        if (tid == 0 && s + STAGES - 1 < KSTEPS) {
            const int p  = s + STAGES - 1;
            const int ps = p & (STAGES - 1);
            if (p >= STAGES) MBAR_WAIT(mb_empty + 8 * ps, ((p >> 2) - 1) & 1);
            MBAR_EXPECT_TX(mb_full + 8 * ps, (uint32_t)STAGE_BYTES);
            const uint32_t sa = tiles + ps * STAGE_BYTES;
            TMA2D(sa,           &tmap_x, p * BK, bm, mb_full + 8 * ps);
            TMA2D(sa + A_BYTES, &tmap_w, p * BK, bn, mb_full + 8 * ps);
        }

        MBAR_WAIT(mb_full + 8 * slot, phase);
        const uint32_t aT = tiles + slot * STAGE_BYTES;
        const uint32_t bT = aT + A_BYTES;

#pragma unroll
        for (int ks = 0; ks < 4; ks++) {
            uint32_t a[4][4], b[2][4];
            const uint32_t acol = (uint32_t)(ks * 32 + ahi);
            const uint32_t bcol = (uint32_t)(ks * 32 + bhi);
#pragma unroll
            for (int mi = 0; mi < 4; mi++)
                ldsm4(a[mi], aT + a_off[mi] + (acol ^ a_xor[mi]));
#pragma unroll
            for (int nj = 0; nj < 2; nj++)
                ldsm4(b[nj], bT + b_off[nj] + (bcol ^ b_xor[nj]));
#pragma unroll
            for (int mi = 0; mi < 4; mi++)
#pragma unroll
                for (int nj = 0; nj < 4; nj++)
                    mma16816(c[mi][nj], a[mi], &b[nj >> 1][(nj & 1) * 2]);
        }

        if (lane == 0) MBAR_ARRIVE(mb_empty + 8 * slot);
        if (++slot == STAGES) { slot = 0; phase ^= 1; }
    }

    // Epilogue: direct register -> global, bias fused. 8B stores, sector-aligned.
    const int gid = lane >> 2;
    const int qid = lane & 3;
#pragma unroll
    for (int nj = 0; nj < 4; nj++) {
        const int col = bn + warp_n * 32 + nj * 8 + qid * 2;
        const float b0 = __ldg(bias + col);
        const float b1 = __ldg(bias + col + 1);
#pragma unroll
        for (int mi = 0; mi < 4; mi++) {
            const int row = bm + warp_m * 64 + mi * 16 + gid;
            float2 v0 = make_float2(c[mi][nj][0] + b0, c[mi][nj][1] + b1);
            float2 v1 = make_float2(c[mi][nj][2] + b0, c[mi][nj][3] + b1);
            *reinterpret_cast<float2*>(out + (size_t)row * Ntot + col)       = v0;
            *reinterpret_cast<float2*>(out + (size_t)(row + 8) * Ntot + col) = v1;
        }
    }
}

// ---------------------------------------------------------------------------
// Host launch
// ---------------------------------------------------------------------------
typedef CUresult (*EncodeTiledFn)(
    CUtensorMap*, CUtensorMapDataType, cuuint32_t, void*,
    const cuuint64_t*, const cuuint64_t*, const cuuint32_t*, const cuuint32_t*,
    CUtensorMapInterleave, CUtensorMapSwizzle, CUtensorMapL2promotion,
    CUtensorMapFloatOOBfill);

extern "C" void kernel_launch(void* const* d_in, const int* in_sizes, int n_in,
                              void* d_out, int out_size) {
    const float* x    = (const float*)d_in[0];  // [8192, 4096]
    const float* W    = (const float*)d_in[1];  // [4096, 4096]
    const float* bias = (const float*)d_in[2];  // [4096]
    const float* down = (const float*)d_in[3];  // [4096, 16]
    const float* up   = (const float*)d_in[4];  // [16, 4096]
    float* out = (float*)d_out;                 // [8192, 4096]
    (void)in_sizes; (void)n_in; (void)out_size;

    static EncodeTiledFn enc = nullptr;
    if (!enc) {
        void* p = nullptr;
        cudaDriverEntryPointQueryResult qr;
        cudaGetDriverEntryPointByVersion("cuTensorMapEncodeTiled", &p, 12000,
                                         cudaEnableDefault, &qr);
        enc = (EncodeTiledFn)p;
    }
    void* xh_ptr = nullptr, *wh_ptr = nullptr;
    cudaGetSymbolAddress(&xh_ptr, g_xh);
    cudaGetSymbolAddress(&wh_ptr, g_wh);

    CUtensorMap mx, mw;
    {
        cuuint64_t dims[2]    = {(cuuint64_t)Ktot, (cuuint64_t)Mtot};
        cuuint64_t strides[1] = {(cuuint64_t)Ktot * 2};
        cuuint32_t box[2]     = {(cuuint32_t)BK, (cuuint32_t)BM};
        cuuint32_t es[2]      = {1, 1};
        enc(&mx, CU_TENSOR_MAP_DATA_TYPE_FLOAT16, 2, xh_ptr,
            dims, strides, box, es,
            CU_TENSOR_MAP_INTERLEAVE_NONE, CU_TENSOR_MAP_SWIZZLE_128B,
            CU_TENSOR_MAP_L2_PROMOTION_L2_128B, CU_TENSOR_MAP_FLOAT_OOB_FILL_NONE);

        dims[1] = (cuuint64_t)Ntot;
        box[1]  = (cuuint32_t)BN;
        enc(&mw, CU_TENSOR_MAP_DATA_TYPE_FLOAT16, 2, wh_ptr,
            dims, strides, box, es,
            CU_TENSOR_MAP_INTERLEAVE_NONE, CU_TENSOR_MAP_SWIZZLE_128B,
            CU_TENSOR_MAP_L2_PROMOTION_L2_128B, CU_TENSOR_MAP_FLOAT_OOB_FILL_NONE);
    }

    cudaFuncSetAttribute(lora_gemm_hmma,
                         cudaFuncAttributeMaxDynamicSharedMemorySize, SMEM_ALLOC);

    prep_kernel<<<Ntot + XBLOCKS, 1024>>>(W, down, up, x);

    dim3 grid(Ntot / BN, Mtot / BM);  // (32, 32) = 1024 CTAs
    lora_gemm_hmma<<<grid, 512, SMEM_ALLOC>>>(mx, mw, bias, out);
}

// round 7
// speedup vs baseline: 5.8163x; 1.0584x over previous
#include <cuda_runtime.h>
#include <cuda.h>
#include <cuda_fp16.h>
#include <cstdint>
#include <cstddef>

// ---------------------------------------------------------------------------
// Problem shape (fixed by dataset)
// ---------------------------------------------------------------------------
static constexpr int Mtot = 8192;   // B*S
static constexpr int Ntot = 4096;   // OUT
static constexpr int Ktot = 4096;   // IN
static constexpr int RANK = 16;

// GEMM tiling (R5 known-good): 256x128x64 CTA, 512 threads, 4 stages.
static constexpr int BM = 256;
static constexpr int BN = 128;
static constexpr int BK = 64;               // 64 fp16 = 128B row = SW128 atom
static constexpr int KSTEPS = Ktot / BK;    // 64
static constexpr int STAGES = 4;

static constexpr int A_BYTES = BM * BK * 2;            // 32 KB
static constexpr int B_BYTES = BN * BK * 2;            // 16 KB
static constexpr int STAGE_BYTES = A_BYTES + B_BYTES;  // 48 KB
static constexpr int SMEM_ALLOC = 2048 + STAGES * STAGE_BYTES;  // 198656 B

// fp16 scratch: W' = W + down@up, and x converted
__device__ __align__(1024) __half g_wh[(size_t)Ntot * Ktot];
__device__ __align__(1024) __half g_xh[(size_t)Mtot * Ktot];

// ---------------------------------------------------------------------------
// PTX helpers (non-'a' instructions only: sm_90 TMA + sm_80 mma)
// ---------------------------------------------------------------------------
__device__ __forceinline__ uint32_t s2u(const void* p) {
    uint32_t a;
    asm("{ .reg .u64 t; cvta.to.shared.u64 t, %1; cvt.u32.u64 %0, t; }"
        : "=r"(a) : "l"(p));
    return a;
}

#define MBAR_INIT(addr, cnt) \
    asm volatile("mbarrier.init.shared.b64 [%0], %1;" :: "r"(addr), "r"(cnt) : "memory")

#define MBAR_EXPECT_TX(addr, bytes) \
    asm volatile("mbarrier.arrive.expect_tx.shared.b64 _, [%0], %1;" \
                 :: "r"(addr), "r"(bytes) : "memory")

#define MBAR_ARRIVE(addr) \
    asm volatile("mbarrier.arrive.shared.b64 _, [%0];" :: "r"(addr) : "memory")

#define MBAR_WAIT(addr, parity) do {                                          \
    uint32_t _mb = (addr); uint32_t _ph = (parity); uint32_t _done;           \
    asm volatile("{\n\t.reg .pred p;\n\t"                                     \
        "mbarrier.try_wait.parity.acquire.cta.shared::cta.b64 p, [%1], %2;\n\t" \
        "selp.b32 %0, 1, 0, p;\n\t}"                                          \
        : "=r"(_done) : "r"(_mb), "r"(_ph) : "memory");                       \
    if (!_done) {                                                             \
        asm volatile("{\n\t.reg .pred P1;\n\t"                                \
            "WL_%=:\n\t"                                                      \
            "mbarrier.try_wait.parity.acquire.cta.shared::cta.b64 P1, [%0], %1, 0x989680;\n\t" \
            "@P1 bra.uni WD_%=;\n\t"                                          \
            "bra.uni WL_%=;\n\t"                                              \
            "WD_%=:\n\t}" :: "r"(_mb), "r"(_ph) : "memory");                  \
    }                                                                         \
} while (0)

#define TMA2D(dst, map, cx, cy, mbar)                                         \
    asm volatile("cp.async.bulk.tensor.2d.shared::cta.global.tile"            \
                 ".mbarrier::complete_tx::bytes [%0], [%1, {%2, %3}], [%4];"  \
                 :: "r"(dst), "l"(map), "r"(cx), "r"(cy), "r"(mbar) : "memory")

__device__ __forceinline__ void ldsm4(uint32_t* r, uint32_t addr) {
    asm volatile("ldmatrix.sync.aligned.m8n8.x4.shared.b16 {%0,%1,%2,%3}, [%4];"
                 : "=r"(r[0]), "=r"(r[1]), "=r"(r[2]), "=r"(r[3]) : "r"(addr));
}

__device__ __forceinline__ void mma16816(float* c, const uint32_t* a, const uint32_t* b) {
    asm volatile(
        "mma.sync.aligned.m16n8k16.row.col.f32.f16.f16.f32 "
        "{%0,%1,%2,%3}, {%4,%5,%6,%7}, {%8,%9}, {%0,%1,%2,%3};"
        : "+f"(c[0]), "+f"(c[1]), "+f"(c[2]), "+f"(c[3])
        : "r"(a[0]), "r"(a[1]), "r"(a[2]), "r"(a[3]), "r"(b[0]), "r"(b[1]));
}

__device__ __forceinline__ uint2 pack_h4(float a, float b, float cc, float d) {
    __half2 h01 = __floats2half2_rn(a, b);
    __half2 h23 = __floats2half2_rn(cc, d);
    uint2 pk;
    pk.x = *reinterpret_cast<const uint32_t*>(&h01);
    pk.y = *reinterpret_cast<const uint32_t*>(&h23);
    return pk;
}

// ---------------------------------------------------------------------------
// Kernel 1 (merged prep):
//  blocks [0, WBLOCKS): fold W' = W + down@up -> fp16, 4 rows per block
//    (amortizes the 16 'up' loads across 4 output rows; 'down' staged in smem)
//  blocks [WBLOCKS, WBLOCKS+XBLOCKS): convert x -> fp16, 4 float4 per thread
// ---------------------------------------------------------------------------
static constexpr int WROWS   = 4;
static constexpr int WBLOCKS = Ntot / WROWS;                     // 1024
static constexpr int XBLOCKS = (Mtot * Ktot / 4) / (1024 * 4);   // 2048

__global__ __launch_bounds__(1024, 1)
void prep_kernel(const float* __restrict__ W,
                 const float* __restrict__ down,
                 const float* __restrict__ up,
                 const float* __restrict__ x) {
    if (blockIdx.x < (unsigned)WBLOCKS) {
        __shared__ float d_s[WROWS * RANK];
        const int o0 = blockIdx.x * WROWS;
        const int i4 = threadIdx.x;  // float4 column index, 0..1023

        if (threadIdx.x < WROWS * RANK)
            d_s[threadIdx.x] = down[o0 * RANK + threadIdx.x];
        __syncthreads();

        float4 acc[WROWS];
#pragma unroll
        for (int j = 0; j < WROWS; j++)
            acc[j] = reinterpret_cast<const float4*>(W + (size_t)(o0 + j) * Ktot)[i4];

#pragma unroll 4
        for (int r = 0; r < RANK; r++) {
            float4 u = reinterpret_cast<const float4*>(up + (size_t)r * Ktot)[i4];
#pragma unroll
            for (int j = 0; j < WROWS; j++) {
                const float dj = d_s[j * RANK + r];
                acc[j].x = fmaf(dj, u.x, acc[j].x);
                acc[j].y = fmaf(dj, u.y, acc[j].y);
                acc[j].z = fmaf(dj, u.z, acc[j].z);
                acc[j].w = fmaf(dj, u.w, acc[j].w);
            }
        }
#pragma unroll
        for (int j = 0; j < WROWS; j++)
            *reinterpret_cast<uint2*>(g_wh + (size_t)(o0 + j) * Ktot + (size_t)i4 * 4) =
                pack_h4(acc[j].x, acc[j].y, acc[j].z, acc[j].w);
    } else {
        const size_t blk = blockIdx.x - WBLOCKS;
        size_t idx = (blk * 1024 + threadIdx.x) * 4;   // float4 index
        float4 v[4];
#pragma unroll
        for (int j = 0; j < 4; j++)
            v[j] = reinterpret_cast<const float4*>(x)[idx + j];
        uint2 pk[4];
#pragma unroll
        for (int j = 0; j < 4; j++)
            pk[j] = pack_h4(v[j].x, v[j].y, v[j].z, v[j].w);
#pragma unroll
        for (int j = 0; j < 4; j++)
            *reinterpret_cast<uint2*>(g_xh + (idx + j) * 4) = pk[j];
    }
}

// ---------------------------------------------------------------------------
// Kernel 2 (R5 known-good, unchanged): out = x @ W'^T + bias.
// fp16 HMMA, TMA 4-stage pipeline. CTA 256x128x64, 512 threads (16 warps).
// ---------------------------------------------------------------------------
__global__ __launch_bounds__(512, 1)
void lora_gemm_hmma(const __grid_constant__ CUtensorMap tmap_x,
                    const __grid_constant__ CUtensorMap tmap_w,
                    const float* __restrict__ bias,
                    float* __restrict__ out)
{
    extern __shared__ char smraw[];
    const uint32_t raw  = s2u(smraw);
    const uint32_t base = (raw + 1023u) & ~1023u;

    const uint32_t mb_full  = base;        // 4 x 8B
    const uint32_t mb_empty = base + 64;   // 4 x 8B
    const uint32_t tiles    = base + 1024;

    const int tid  = threadIdx.x;
    const int wid  = tid >> 5;
    const int lane = tid & 31;
    const int bm = blockIdx.y * BM;
    const int bn = blockIdx.x * BN;
    const int warp_m = wid >> 2;   // 0..3 -> 64 rows
    const int warp_n = wid & 3;    // 0..3 -> 32 cols

    if (tid == 0) {
        for (int s = 0; s < STAGES; s++) {
            MBAR_INIT(mb_full  + 8 * s, 1);
            MBAR_INIT(mb_empty + 8 * s, 16);   // one arrive per warp
        }
    }
    __syncthreads();

    // Prologue: stage 0..STAGES-2
    if (tid == 0) {
#pragma unroll
        for (int s = 0; s < STAGES - 1; s++) {
            MBAR_EXPECT_TX(mb_full + 8 * s, (uint32_t)STAGE_BYTES);
            const uint32_t sa = tiles + s * STAGE_BYTES;
            TMA2D(sa,           &tmap_x, s * BK, bm, mb_full + 8 * s);
            TMA2D(sa + A_BYTES, &tmap_w, s * BK, bn, mb_full + 8 * s);
        }
    }

    float c[4][4][4];
#pragma unroll
    for (int i = 0; i < 4; i++)
#pragma unroll
        for (int j = 0; j < 4; j++)
#pragma unroll
            for (int k = 0; k < 4; k++) c[i][j][k] = 0.0f;

    // Per-lane smem addressing (SW128: XOR const = (row&7)<<4, rows are 128B)
    const int lr16 = lane & 15;
    const int ahi  = (lane >> 4) << 4;            // A col byte offset: 0 / 16
    uint32_t a_off[4], a_xor[4];
#pragma unroll
    for (int mi = 0; mi < 4; mi++) {
        const int r = warp_m * 64 + mi * 16 + lr16;
        a_off[mi] = (uint32_t)r * 128;
        a_xor[mi] = (uint32_t)((r & 7) << 4);
    }
    const int brlo = (lane & 7) + ((lane >> 4) << 3);  // B row-in-16
    const int bhi  = ((lane >> 3) & 1) << 4;           // B col byte: 0 / 16
    uint32_t b_off[2], b_xor[2];
#pragma unroll
    for (int nj = 0; nj < 2; nj++) {
        const int r = warp_n * 32 + nj * 16 + brlo;
        b_off[nj] = (uint32_t)r * 128;
        b_xor[nj] = (uint32_t)((r & 7) << 4);
    }

    int slot = 0, phase = 0;
    for (int s = 0; s < KSTEPS; s++) {
        if (tid == 0 && s + STAGES - 1 < KSTEPS) {
            const int p  = s + STAGES - 1;
            const int ps = p & (STAGES - 1);
            if (p >= STAGES) MBAR_WAIT(mb_empty + 8 * ps, ((p >> 2) - 1) & 1);
            MBAR_EXPECT_TX(mb_full + 8 * ps, (uint32_t)STAGE_BYTES);
            const uint32_t sa = tiles + ps * STAGE_BYTES;
            TMA2D(sa,           &tmap_x, p * BK, bm, mb_full + 8 * ps);
            TMA2D(sa + A_BYTES, &tmap_w, p * BK, bn, mb_full + 8 * ps);
        }

        MBAR_WAIT(mb_full + 8 * slot, phase);
        const uint32_t aT = tiles + slot * STAGE_BYTES;
        const uint32_t bT = aT + A_BYTES;

#pragma unroll
        for (int ks = 0; ks < 4; ks++) {
            uint32_t a[4][4], b[2][4];
            const uint32_t acol = (uint32_t)(ks * 32 + ahi);
            const uint32_t bcol = (uint32_t)(ks * 32 + bhi);
#pragma unroll
            for (int mi = 0; mi < 4; mi++)
                ldsm4(a[mi], aT + a_off[mi] + (acol ^ a_xor[mi]));
#pragma unroll
            for (int nj = 0; nj < 2; nj++)
                ldsm4(b[nj], bT + b_off[nj] + (bcol ^ b_xor[nj]));
#pragma unroll
            for (int mi = 0; mi < 4; mi++)
#pragma unroll
                for (int nj = 0; nj < 4; nj++)
                    mma16816(c[mi][nj], a[mi], &b[nj >> 1][(nj & 1) * 2]);
        }

        if (lane == 0) MBAR_ARRIVE(mb_empty + 8 * slot);
        if (++slot == STAGES) { slot = 0; phase ^= 1; }
    }

    // Epilogue: direct register -> global, bias fused. 8B sector-aligned stores.
    const int gid = lane >> 2;
    const int qid = lane & 3;
#pragma unroll
    for (int nj = 0; nj < 4; nj++) {
        const int col = bn + warp_n * 32 + nj * 8 + qid * 2;
        const float b0 = __ldg(bias + col);
        const float b1 = __ldg(bias + col + 1);
#pragma unroll
        for (int mi = 0; mi < 4; mi++) {
            const int row = bm + warp_m * 64 + mi * 16 + gid;
            float2 v0 = make_float2(c[mi][nj][0] + b0, c[mi][nj][1] + b1);
            float2 v1 = make_float2(c[mi][nj][2] + b0, c[mi][nj][3] + b1);
            *reinterpret_cast<float2*>(out + (size_t)row * Ntot + col)       = v0;
            *reinterpret_cast<float2*>(out + (size_t)(row + 8) * Ntot + col) = v1;
        }
    }
}

// ---------------------------------------------------------------------------
// Host launch
// ---------------------------------------------------------------------------
typedef CUresult (*EncodeTiledFn)(
    CUtensorMap*, CUtensorMapDataType, cuuint32_t, void*,
    const cuuint64_t*, const cuuint64_t*, const cuuint32_t*, const cuuint32_t*,
    CUtensorMapInterleave, CUtensorMapSwizzle, CUtensorMapL2promotion,
    CUtensorMapFloatOOBfill);

extern "C" void kernel_launch(void* const* d_in, const int* in_sizes, int n_in,
                              void* d_out, int out_size) {
    const float* x    = (const float*)d_in[0];  // [8192, 4096]
    const float* W    = (const float*)d_in[1];  // [4096, 4096]
    const float* bias = (const float*)d_in[2];  // [4096]
    const float* down = (const float*)d_in[3];  // [4096, 16]
    const float* up   = (const float*)d_in[4];  // [16, 4096]
    float* out = (float*)d_out;                 // [8192, 4096]
    (void)in_sizes; (void)n_in; (void)out_size;

    static EncodeTiledFn enc = nullptr;
    if (!enc) {
        void* p = nullptr;
        cudaDriverEntryPointQueryResult qr;
        cudaGetDriverEntryPointByVersion("cuTensorMapEncodeTiled", &p, 12000,
                                         cudaEnableDefault, &qr);
        enc = (EncodeTiledFn)p;
    }
    void* xh_ptr = nullptr, *wh_ptr = nullptr;
    cudaGetSymbolAddress(&xh_ptr, g_xh);
    cudaGetSymbolAddress(&wh_ptr, g_wh);

    CUtensorMap mx, mw;
    {
        cuuint64_t dims[2]    = {(cuuint64_t)Ktot, (cuuint64_t)Mtot};
        cuuint64_t strides[1] = {(cuuint64_t)Ktot * 2};
        cuuint32_t box[2]     = {(cuuint32_t)BK, (cuuint32_t)BM};
        cuuint32_t es[2]      = {1, 1};
        enc(&mx, CU_TENSOR_MAP_DATA_TYPE_FLOAT16, 2, xh_ptr,
            dims, strides, box, es,
            CU_TENSOR_MAP_INTERLEAVE_NONE, CU_TENSOR_MAP_SWIZZLE_128B,
            CU_TENSOR_MAP_L2_PROMOTION_L2_128B, CU_TENSOR_MAP_FLOAT_OOB_FILL_NONE);

        dims[1] = (cuuint64_t)Ntot;
        box[1]  = (cuuint32_t)BN;
        enc(&mw, CU_TENSOR_MAP_DATA_TYPE_FLOAT16, 2, wh_ptr,
            dims, strides, box, es,
            CU_TENSOR_MAP_INTERLEAVE_NONE, CU_TENSOR_MAP_SWIZZLE_128B,
            CU_TENSOR_MAP_L2_PROMOTION_L2_128B, CU_TENSOR_MAP_FLOAT_OOB_FILL_NONE);
    }

    cudaFuncSetAttribute(lora_gemm_hmma,
                         cudaFuncAttributeMaxDynamicSharedMemorySize, SMEM_ALLOC);

    prep_kernel<<<WBLOCKS + XBLOCKS, 1024>>>(W, down, up, x);

    dim3 grid(Ntot / BN, Mtot / BM);  // (32, 32) = 1024 CTAs
    lora_gemm_hmma<<<grid, 512, SMEM_ALLOC>>>(mx, mw, bias, out);
}

// round 8
// speedup vs baseline: 6.1388x; 1.0554x over previous
#include <cuda_runtime.h>
#include <cuda.h>
#include <cuda_fp16.h>
#include <cstdint>
#include <cstddef>

// ---------------------------------------------------------------------------
// Problem shape (fixed by dataset)
// ---------------------------------------------------------------------------
static constexpr int Mtot = 8192;   // B*S
static constexpr int Ntot = 4096;   // OUT
static constexpr int Ktot = 4096;   // IN
static constexpr int RANK = 16;

// GEMM tiling: CTA 256x128x64 (same as R7), but 8 warps (4Mx2N), warp 64x64.
static constexpr int BM = 256;
static constexpr int BN = 128;
static constexpr int BK = 64;               // 64 fp16 = 128B row = SW128 atom
static constexpr int KSTEPS = Ktot / BK;    // 64
static constexpr int STAGES = 4;

static constexpr int A_BYTES = BM * BK * 2;            // 32 KB
static constexpr int B_BYTES = BN * BK * 2;            // 16 KB
static constexpr int STAGE_BYTES = A_BYTES + B_BYTES;  // 48 KB
static constexpr int SMEM_ALLOC = 2048 + STAGES * STAGE_BYTES;  // 198656 B

// fp16 scratch: W' = W + down@up, and x converted
__device__ __align__(1024) __half g_wh[(size_t)Ntot * Ktot];
__device__ __align__(1024) __half g_xh[(size_t)Mtot * Ktot];

// ---------------------------------------------------------------------------
// PTX helpers (non-'a' instructions only: sm_90 TMA + sm_80 mma)
// ---------------------------------------------------------------------------
__device__ __forceinline__ uint32_t s2u(const void* p) {
    uint32_t a;
    asm("{ .reg .u64 t; cvta.to.shared.u64 t, %1; cvt.u32.u64 %0, t; }"
        : "=r"(a) : "l"(p));
    return a;
}

#define MBAR_INIT(addr, cnt) \
    asm volatile("mbarrier.init.shared.b64 [%0], %1;" :: "r"(addr), "r"(cnt) : "memory")

#define MBAR_EXPECT_TX(addr, bytes) \
    asm volatile("mbarrier.arrive.expect_tx.shared.b64 _, [%0], %1;" \
                 :: "r"(addr), "r"(bytes) : "memory")

#define MBAR_ARRIVE(addr) \
    asm volatile("mbarrier.arrive.shared.b64 _, [%0];" :: "r"(addr) : "memory")

#define MBAR_WAIT(addr, parity) do {                                          \
    uint32_t _mb = (addr); uint32_t _ph = (parity); uint32_t _done;           \
    asm volatile("{\n\t.reg .pred p;\n\t"                                     \
        "mbarrier.try_wait.parity.acquire.cta.shared::cta.b64 p, [%1], %2;\n\t" \
        "selp.b32 %0, 1, 0, p;\n\t}"                                          \
        : "=r"(_done) : "r"(_mb), "r"(_ph) : "memory");                       \
    if (!_done) {                                                             \
        asm volatile("{\n\t.reg .pred P1;\n\t"                                \
            "WL_%=:\n\t"                                                      \
            "mbarrier.try_wait.parity.acquire.cta.shared::cta.b64 P1, [%0], %1, 0x989680;\n\t" \
            "@P1 bra.uni WD_%=;\n\t"                                          \
            "bra.uni WL_%=;\n\t"                                              \
            "WD_%=:\n\t}" :: "r"(_mb), "r"(_ph) : "memory");                  \
    }                                                                         \
} while (0)

#define TMA2D(dst, map, cx, cy, mbar)                                         \
    asm volatile("cp.async.bulk.tensor.2d.shared::cta.global.tile"            \
                 ".mbarrier::complete_tx::bytes [%0], [%1, {%2, %3}], [%4];"  \
                 :: "r"(dst), "l"(map), "r"(cx), "r"(cy), "r"(mbar) : "memory")

__device__ __forceinline__ void ldsm4(uint32_t* r, uint32_t addr) {
    asm volatile("ldmatrix.sync.aligned.m8n8.x4.shared.b16 {%0,%1,%2,%3}, [%4];"
                 : "=r"(r[0]), "=r"(r[1]), "=r"(r[2]), "=r"(r[3]) : "r"(addr));
}

__device__ __forceinline__ void mma16816(float* c, const uint32_t* a, const uint32_t* b) {
    asm volatile(
        "mma.sync.aligned.m16n8k16.row.col.f32.f16.f16.f32 "
        "{%0,%1,%2,%3}, {%4,%5,%6,%7}, {%8,%9}, {%0,%1,%2,%3};"
        : "+f"(c[0]), "+f"(c[1]), "+f"(c[2]), "+f"(c[3])
        : "r"(a[0]), "r"(a[1]), "r"(a[2]), "r"(a[3]), "r"(b[0]), "r"(b[1]));
}

__device__ __forceinline__ uint2 pack_h4(float a, float b, float cc, float d) {
    __half2 h01 = __floats2half2_rn(a, b);
    __half2 h23 = __floats2half2_rn(cc, d);
    uint2 pk;
    pk.x = *reinterpret_cast<const uint32_t*>(&h01);
    pk.y = *reinterpret_cast<const uint32_t*>(&h23);
    return pk;
}

// ---------------------------------------------------------------------------
// Kernel 1 (merged prep, unchanged from R7):
//  blocks [0, WBLOCKS): fold W' = W + down@up -> fp16, 4 rows per block
//  blocks [WBLOCKS, WBLOCKS+XBLOCKS): convert x -> fp16, 4 float4 per thread
// ---------------------------------------------------------------------------
static constexpr int WROWS   = 4;
static constexpr int WBLOCKS = Ntot / WROWS;                     // 1024
static constexpr int XBLOCKS = (Mtot * Ktot / 4) / (1024 * 4);   // 2048

__global__ __launch_bounds__(1024, 1)
void prep_kernel(const float* __restrict__ W,
                 const float* __restrict__ down,
                 const float* __restrict__ up,
                 const float* __restrict__ x) {
    if (blockIdx.x < (unsigned)WBLOCKS) {
        __shared__ float d_s[WROWS * RANK];
        const int o0 = blockIdx.x * WROWS;
        const int i4 = threadIdx.x;  // float4 column index, 0..1023

        if (threadIdx.x < WROWS * RANK)
            d_s[threadIdx.x] = down[o0 * RANK + threadIdx.x];
        __syncthreads();

        float4 acc[WROWS];
#pragma unroll
        for (int j = 0; j < WROWS; j++)
            acc[j] = reinterpret_cast<const float4*>(W + (size_t)(o0 + j) * Ktot)[i4];

#pragma unroll 4
        for (int r = 0; r < RANK; r++) {
            float4 u = reinterpret_cast<const float4*>(up + (size_t)r * Ktot)[i4];
#pragma unroll
            for (int j = 0; j < WROWS; j++) {
                const float dj = d_s[j * RANK + r];
                acc[j].x = fmaf(dj, u.x, acc[j].x);
                acc[j].y = fmaf(dj, u.y, acc[j].y);
                acc[j].z = fmaf(dj, u.z, acc[j].z);
                acc[j].w = fmaf(dj, u.w, acc[j].w);
            }
        }
#pragma unroll
        for (int j = 0; j < WROWS; j++)
            *reinterpret_cast<uint2*>(g_wh + (size_t)(o0 + j) * Ktot + (size_t)i4 * 4) =
                pack_h4(acc[j].x, acc[j].y, acc[j].z, acc[j].w);
    } else {
        const size_t blk = blockIdx.x - WBLOCKS;
        size_t idx = (blk * 1024 + threadIdx.x) * 4;   // float4 index
        float4 v[4];
#pragma unroll
        for (int j = 0; j < 4; j++)
            v[j] = reinterpret_cast<const float4*>(x)[idx + j];
        uint2 pk[4];
#pragma unroll
        for (int j = 0; j < 4; j++)
            pk[j] = pack_h4(v[j].x, v[j].y, v[j].z, v[j].w);
#pragma unroll
        for (int j = 0; j < 4; j++)
            *reinterpret_cast<uint2*>(g_xh + (idx + j) * 4) = pk[j];
    }
}

// ---------------------------------------------------------------------------
// Kernel 2: out = x @ W'^T + bias.  fp16 HMMA, TMA 4-stage pipeline.
// CTA 256x128x64 (same tiles/pipeline as R7), 256 threads, 8 warps (4Mx2N),
// warp tile 64x64: halves B-operand LDSM traffic per MMA (crossbar relief).
// ---------------------------------------------------------------------------
__global__ __launch_bounds__(256, 1)
void lora_gemm_hmma(const __grid_constant__ CUtensorMap tmap_x,
                    const __grid_constant__ CUtensorMap tmap_w,
                    const float* __restrict__ bias,
                    float* __restrict__ out)
{
    extern __shared__ char smraw[];
    const uint32_t raw  = s2u(smraw);
    const uint32_t base = (raw + 1023u) & ~1023u;

    const uint32_t mb_full  = base;        // 4 x 8B
    const uint32_t mb_empty = base + 64;   // 4 x 8B
    const uint32_t tiles    = base + 1024;

    const int tid  = threadIdx.x;
    const int wid  = tid >> 5;
    const int lane = tid & 31;
    const int bm = blockIdx.y * BM;
    const int bn = blockIdx.x * BN;
    const int warp_m = wid >> 1;   // 0..3 -> 64 rows each
    const int warp_n = wid & 1;    // 0..1 -> 64 cols each

    if (tid == 0) {
        for (int s = 0; s < STAGES; s++) {
            MBAR_INIT(mb_full  + 8 * s, 1);
            MBAR_INIT(mb_empty + 8 * s, 8);   // one arrive per warp
        }
    }
    __syncthreads();

    // Prologue: stage 0..STAGES-2  (identical to R7)
    if (tid == 0) {
#pragma unroll
        for (int s = 0; s < STAGES - 1; s++) {
            MBAR_EXPECT_TX(mb_full + 8 * s, (uint32_t)STAGE_BYTES);
            const uint32_t sa = tiles + s * STAGE_BYTES;
            TMA2D(sa,           &tmap_x, s * BK, bm, mb_full + 8 * s);
            TMA2D(sa + A_BYTES, &tmap_w, s * BK, bn, mb_full + 8 * s);
        }
    }

    float c[4][8][4];
#pragma unroll
    for (int i = 0; i < 4; i++)
#pragma unroll
        for (int j = 0; j < 8; j++)
#pragma unroll
            for (int k = 0; k < 4; k++) c[i][j][k] = 0.0f;

    // Per-lane smem addressing (SW128: XOR const = (row&7)<<4, rows are 128B)
    const int lr16 = lane & 15;
    const int ahi  = (lane >> 4) << 4;            // A col byte offset: 0 / 16
    uint32_t a_off[4], a_xor[4];
#pragma unroll
    for (int mi = 0; mi < 4; mi++) {
        const int r = warp_m * 64 + mi * 16 + lr16;
        a_off[mi] = (uint32_t)r * 128;
        a_xor[mi] = (uint32_t)((r & 7) << 4);
    }
    const int brlo = (lane & 7) + ((lane >> 4) << 3);  // B row-in-16
    const int bhi  = ((lane >> 3) & 1) << 4;           // B col byte: 0 / 16
    uint32_t b_off[4], b_xor[4];
#pragma unroll
    for (int nj = 0; nj < 4; nj++) {
        const int r = warp_n * 64 + nj * 16 + brlo;
        b_off[nj] = (uint32_t)r * 128;
        b_xor[nj] = (uint32_t)((r & 7) << 4);
    }

    int slot = 0, phase = 0;
    for (int s = 0; s < KSTEPS; s++) {
        // Producer (identical to R7)
        if (tid == 0 && s + STAGES - 1 < KSTEPS) {
            const int p  = s + STAGES - 1;
            const int ps = p & (STAGES - 1);
            if (p >= STAGES) MBAR_WAIT(mb_empty + 8 * ps, ((p >> 2) - 1) & 1);
            MBAR_EXPECT_TX(mb_full + 8 * ps, (uint32_t)STAGE_BYTES);
            const uint32_t sa = tiles + ps * STAGE_BYTES;
            TMA2D(sa,           &tmap_x, p * BK, bm, mb_full + 8 * ps);
            TMA2D(sa + A_BYTES, &tmap_w, p * BK, bn, mb_full + 8 * ps);
        }

        MBAR_WAIT(mb_full + 8 * slot, phase);
        const uint32_t aT = tiles + slot * STAGE_BYTES;
        const uint32_t bT = aT + A_BYTES;

#pragma unroll
        for (int ks = 0; ks < 4; ks++) {
            uint32_t a[4][4], b[4][4];
            const uint32_t acol = (uint32_t)(ks * 32 + ahi);
            const uint32_t bcol = (uint32_t)(ks * 32 + bhi);
#pragma unroll
            for (int mi = 0; mi < 4; mi++)
                ldsm4(a[mi], aT + a_off[mi] + (acol ^ a_xor[mi]));
#pragma unroll
            for (int nj = 0; nj < 4; nj++)
                ldsm4(b[nj], bT + b_off[nj] + (bcol ^ b_xor[nj]));
#pragma unroll
            for (int mi = 0; mi < 4; mi++)
#pragma unroll
                for (int nj = 0; nj < 8; nj++)
                    mma16816(c[mi][nj], a[mi], &b[nj >> 1][(nj & 1) * 2]);
        }

        if (lane == 0) MBAR_ARRIVE(mb_empty + 8 * slot);
        if (++slot == STAGES) { slot = 0; phase ^= 1; }
    }

    // Epilogue: direct register -> global, bias fused. 8B sector-aligned stores.
    const int gid = lane >> 2;
    const int qid = lane & 3;
#pragma unroll
    for (int nj = 0; nj < 8; nj++) {
        const int col = bn + warp_n * 64 + nj * 8 + qid * 2;
        const float b0 = __ldg(bias + col);
        const float b1 = __ldg(bias + col + 1);
#pragma unroll
        for (int mi = 0; mi < 4; mi++) {
            const int row = bm + warp_m * 64 + mi * 16 + gid;
            float2 v0 = make_float2(c[mi][nj][0] + b0, c[mi][nj][1] + b1);
            float2 v1 = make_float2(c[mi][nj][2] + b0, c[mi][nj][3] + b1);
            *reinterpret_cast<float2*>(out + (size_t)row * Ntot + col)       = v0;
            *reinterpret_cast<float2*>(out + (size_t)(row + 8) * Ntot + col) = v1;
        }
    }
}

// ---------------------------------------------------------------------------
// Host launch
// ---------------------------------------------------------------------------
typedef CUresult (*EncodeTiledFn)(
    CUtensorMap*, CUtensorMapDataType, cuuint32_t, void*,
    const cuuint64_t*, const cuuint64_t*, const cuuint32_t*, const cuuint32_t*,
    CUtensorMapInterleave, CUtensorMapSwizzle, CUtensorMapL2promotion,
    CUtensorMapFloatOOBfill);

extern "C" void kernel_launch(void* const* d_in, const int* in_sizes, int n_in,
                              void* d_out, int out_size) {
    const float* x    = (const float*)d_in[0];  // [8192, 4096]
    const float* W    = (const float*)d_in[1];  // [4096, 4096]
    const float* bias = (const float*)d_in[2];  // [4096]
    const float* down = (const float*)d_in[3];  // [4096, 16]
    const float* up   = (const float*)d_in[4];  // [16, 4096]
    float* out = (float*)d_out;                 // [8192, 4096]
    (void)in_sizes; (void)n_in; (void)out_size;

    static EncodeTiledFn enc = nullptr;
    if (!enc) {
        void* p = nullptr;
        cudaDriverEntryPointQueryResult qr;
        cudaGetDriverEntryPointByVersion("cuTensorMapEncodeTiled", &p, 12000,
                                         cudaEnableDefault, &qr);
        enc = (EncodeTiledFn)p;
    }
    void* xh_ptr = nullptr, *wh_ptr = nullptr;
    cudaGetSymbolAddress(&xh_ptr, g_xh);
    cudaGetSymbolAddress(&wh_ptr, g_wh);

    CUtensorMap mx, mw;
    {
        cuuint64_t dims[2]    = {(cuuint64_t)Ktot, (cuuint64_t)Mtot};
        cuuint64_t strides[1] = {(cuuint64_t)Ktot * 2};
        cuuint32_t box[2]     = {(cuuint32_t)BK, (cuuint32_t)BM};
        cuuint32_t es[2]      = {1, 1};
        enc(&mx, CU_TENSOR_MAP_DATA_TYPE_FLOAT16, 2, xh_ptr,
            dims, strides, box, es,
            CU_TENSOR_MAP_INTERLEAVE_NONE, CU_TENSOR_MAP_SWIZZLE_128B,
            CU_TENSOR_MAP_L2_PROMOTION_L2_128B, CU_TENSOR_MAP_FLOAT_OOB_FILL_NONE);

        dims[1] = (cuuint64_t)Ntot;
        box[1]  = (cuuint32_t)BN;
        enc(&mw, CU_TENSOR_MAP_DATA_TYPE_FLOAT16, 2, wh_ptr,
            dims, strides, box, es,
            CU_TENSOR_MAP_INTERLEAVE_NONE, CU_TENSOR_MAP_SWIZZLE_128B,
            CU_TENSOR_MAP_L2_PROMOTION_L2_128B, CU_TENSOR_MAP_FLOAT_OOB_FILL_NONE);
    }

    cudaFuncSetAttribute(lora_gemm_hmma,
                         cudaFuncAttributeMaxDynamicSharedMemorySize, SMEM_ALLOC);

    prep_kernel<<<WBLOCKS + XBLOCKS, 1024>>>(W, down, up, x);

    dim3 grid(Ntot / BN, Mtot / BM);  // (32, 32) = 1024 CTAs
    lora_gemm_hmma<<<grid, 256, SMEM_ALLOC>>>(mx, mw, bias, out);
}

// round 9
// speedup vs baseline: 6.2554x; 1.0190x over previous
#include <cuda_runtime.h>
#include <cuda.h>
#include <cuda_fp16.h>
#include <cstdint>
#include <cstddef>

// ---------------------------------------------------------------------------
// Problem shape (fixed by dataset)
// ---------------------------------------------------------------------------
static constexpr int Mtot = 8192;   // B*S
static constexpr int Ntot = 4096;   // OUT
static constexpr int Ktot = 4096;   // IN
static constexpr int RANK = 16;

// GEMM tiling: CTA 256x128x64, 8 warps (4Mx2N), warp tile 64x64 (R8 config).
static constexpr int BM = 256;
static constexpr int BN = 128;
static constexpr int BK = 64;               // 64 fp16 = 128B row = SW128 atom
static constexpr int KSTEPS = Ktot / BK;    // 64
static constexpr int STAGES = 4;
static constexpr int NTILES = (Mtot / BM) * (Ntot / BN);   // 32*32 = 1024

static constexpr int A_BYTES = BM * BK * 2;            // 32 KB
static constexpr int B_BYTES = BN * BK * 2;            // 16 KB
static constexpr int STAGE_BYTES = A_BYTES + B_BYTES;  // 48 KB
static constexpr int SMEM_ALLOC = 2048 + STAGES * STAGE_BYTES;  // 198656 B

// fp16 scratch: W' = W + down@up, and x converted
__device__ __align__(1024) __half g_wh[(size_t)Ntot * Ktot];
__device__ __align__(1024) __half g_xh[(size_t)Mtot * Ktot];

// ---------------------------------------------------------------------------
// PTX helpers (non-'a' instructions only: sm_90 TMA + sm_80 mma)
// ---------------------------------------------------------------------------
__device__ __forceinline__ uint32_t s2u(const void* p) {
    uint32_t a;
    asm("{ .reg .u64 t; cvta.to.shared.u64 t, %1; cvt.u32.u64 %0, t; }"
        : "=r"(a) : "l"(p));
    return a;
}

#define MBAR_INIT(addr, cnt) \
    asm volatile("mbarrier.init.shared.b64 [%0], %1;" :: "r"(addr), "r"(cnt) : "memory")

#define MBAR_EXPECT_TX(addr, bytes) \
    asm volatile("mbarrier.arrive.expect_tx.shared.b64 _, [%0], %1;" \
                 :: "r"(addr), "r"(bytes) : "memory")

#define MBAR_ARRIVE(addr) \
    asm volatile("mbarrier.arrive.shared.b64 _, [%0];" :: "r"(addr) : "memory")

#define MBAR_WAIT(addr, parity) do {                                          \
    uint32_t _mb = (addr); uint32_t _ph = (parity); uint32_t _done;           \
    asm volatile("{\n\t.reg .pred p;\n\t"                                     \
        "mbarrier.try_wait.parity.acquire.cta.shared::cta.b64 p, [%1], %2;\n\t" \
        "selp.b32 %0, 1, 0, p;\n\t}"                                          \
        : "=r"(_done) : "r"(_mb), "r"(_ph) : "memory");                       \
    if (!_done) {                                                             \
        asm volatile("{\n\t.reg .pred P1;\n\t"                                \
            "WL_%=:\n\t"                                                      \
            "mbarrier.try_wait.parity.acquire.cta.shared::cta.b64 P1, [%0], %1, 0x989680;\n\t" \
            "@P1 bra.uni WD_%=;\n\t"                                          \
            "bra.uni WL_%=;\n\t"                                              \
            "WD_%=:\n\t}" :: "r"(_mb), "r"(_ph) : "memory");                  \
    }                                                                         \
} while (0)

#define TMA2D(dst, map, cx, cy, mbar)                                         \
    asm volatile("cp.async.bulk.tensor.2d.shared::cta.global.tile"            \
                 ".mbarrier::complete_tx::bytes [%0], [%1, {%2, %3}], [%4];"  \
                 :: "r"(dst), "l"(map), "r"(cx), "r"(cy), "r"(mbar) : "memory")

__device__ __forceinline__ void ldsm4(uint32_t* r, uint32_t addr) {
    asm volatile("ldmatrix.sync.aligned.m8n8.x4.shared.b16 {%0,%1,%2,%3}, [%4];"
                 : "=r"(r[0]), "=r"(r[1]), "=r"(r[2]), "=r"(r[3]) : "r"(addr));
}

__device__ __forceinline__ void mma16816(float* c, const uint32_t* a, const uint32_t* b) {
    asm volatile(
        "mma.sync.aligned.m16n8k16.row.col.f32.f16.f16.f32 "
        "{%0,%1,%2,%3}, {%4,%5,%6,%7}, {%8,%9}, {%0,%1,%2,%3};"
        : "+f"(c[0]), "+f"(c[1]), "+f"(c[2]), "+f"(c[3])
        : "r"(a[0]), "r"(a[1]), "r"(a[2]), "r"(a[3]), "r"(b[0]), "r"(b[1]));
}

__device__ __forceinline__ uint2 pack_h4(float a, float b, float cc, float d) {
    __half2 h01 = __floats2half2_rn(a, b);
    __half2 h23 = __floats2half2_rn(cc, d);
    uint2 pk;
    pk.x = *reinterpret_cast<const uint32_t*>(&h01);
    pk.y = *reinterpret_cast<const uint32_t*>(&h23);
    return pk;
}

// ---------------------------------------------------------------------------
// Kernel 1 (merged prep, unchanged from R7/R8)
// ---------------------------------------------------------------------------
static constexpr int WROWS   = 4;
static constexpr int WBLOCKS = Ntot / WROWS;                     // 1024
static constexpr int XBLOCKS = (Mtot * Ktot / 4) / (1024 * 4);   // 2048

__global__ __launch_bounds__(1024, 1)
void prep_kernel(const float* __restrict__ W,
                 const float* __restrict__ down,
                 const float* __restrict__ up,
                 const float* __restrict__ x) {
    if (blockIdx.x < (unsigned)WBLOCKS) {
        __shared__ float d_s[WROWS * RANK];
        const int o0 = blockIdx.x * WROWS;
        const int i4 = threadIdx.x;  // float4 column index, 0..1023

        if (threadIdx.x < WROWS * RANK)
            d_s[threadIdx.x] = down[o0 * RANK + threadIdx.x];
        __syncthreads();

        float4 acc[WROWS];
#pragma unroll
        for (int j = 0; j < WROWS; j++)
            acc[j] = reinterpret_cast<const float4*>(W + (size_t)(o0 + j) * Ktot)[i4];

#pragma unroll 4
        for (int r = 0; r < RANK; r++) {
            float4 u = reinterpret_cast<const float4*>(up + (size_t)r * Ktot)[i4];
#pragma unroll
            for (int j = 0; j < WROWS; j++) {
                const float dj = d_s[j * RANK + r];
                acc[j].x = fmaf(dj, u.x, acc[j].x);
                acc[j].y = fmaf(dj, u.y, acc[j].y);
                acc[j].z = fmaf(dj, u.z, acc[j].z);
                acc[j].w = fmaf(dj, u.w, acc[j].w);
            }
        }
#pragma unroll
        for (int j = 0; j < WROWS; j++)
            *reinterpret_cast<uint2*>(g_wh + (size_t)(o0 + j) * Ktot + (size_t)i4 * 4) =
                pack_h4(acc[j].x, acc[j].y, acc[j].z, acc[j].w);
    } else {
        const size_t blk = blockIdx.x - WBLOCKS;
        size_t idx = (blk * 1024 + threadIdx.x) * 4;   // float4 index
        float4 v[4];
#pragma unroll
        for (int j = 0; j < 4; j++)
            v[j] = reinterpret_cast<const float4*>(x)[idx + j];
        uint2 pk[4];
#pragma unroll
        for (int j = 0; j < 4; j++)
            pk[j] = pack_h4(v[j].x, v[j].y, v[j].z, v[j].w);
#pragma unroll
        for (int j = 0; j < 4; j++)
            *reinterpret_cast<uint2*>(g_xh + (idx + j) * 4) = pk[j];
    }
}

// ---------------------------------------------------------------------------
// Kernel 2: persistent-stream GEMM. Each CTA owns tiles cta, cta+grid, ...
// streamed through ONE continuous 4-stage TMA ring: producer runs STAGES-1
// steps ahead across tile boundaries, so tile t+1's stages land during tile
// t's epilogue. Mainloop math identical to R8 (bit-identical results).
// ---------------------------------------------------------------------------
__global__ __launch_bounds__(256, 1)
void lora_gemm_hmma(const __grid_constant__ CUtensorMap tmap_x,
                    const __grid_constant__ CUtensorMap tmap_w,
                    const float* __restrict__ bias,
                    float* __restrict__ out)
{
    extern __shared__ char smraw[];
    const uint32_t raw  = s2u(smraw);
    const uint32_t base = (raw + 1023u) & ~1023u;

    const uint32_t mb_full  = base;        // 4 x 8B
    const uint32_t mb_empty = base + 64;   // 4 x 8B
    const uint32_t tiles    = base + 1024;

    const int tid  = threadIdx.x;
    const int wid  = tid >> 5;
    const int lane = tid & 31;
    const int cta   = blockIdx.x;
    const int gridn = gridDim.x;
    const int warp_m = wid >> 1;   // 0..3 -> 64 rows each
    const int warp_n = wid & 1;    // 0..1 -> 64 cols each

    // Number of tiles this CTA owns; total stream steps
    int nt = 0;
    for (int t = cta; t < NTILES; t += gridn) nt++;
    const int total_steps = nt * KSTEPS;

    if (tid == 0) {
        for (int s = 0; s < STAGES; s++) {
            MBAR_INIT(mb_full  + 8 * s, 1);
            MBAR_INIT(mb_empty + 8 * s, 8);   // one arrive per warp
        }
    }
    __syncthreads();

    // Prologue: issue global steps 0..STAGES-2 of this CTA's stream
    if (tid == 0) {
#pragma unroll
        for (int p = 0; p < STAGES - 1; p++) {
            if (p < total_steps) {
                const int kt = p >> 6;                    // tile index in stream
                const int t  = cta + kt * gridn;
                const int s  = p & (KSTEPS - 1);
                MBAR_EXPECT_TX(mb_full + 8 * p, (uint32_t)STAGE_BYTES);
                const uint32_t sa = tiles + p * STAGE_BYTES;
                TMA2D(sa,           &tmap_x, s * BK, (t >> 5) * BM, mb_full + 8 * p);
                TMA2D(sa + A_BYTES, &tmap_w, s * BK, (t & 31) * BN, mb_full + 8 * p);
            }
        }
    }

    // Per-lane smem addressing (SW128: XOR const = (row&7)<<4, rows are 128B)
    const int lr16 = lane & 15;
    const int ahi  = (lane >> 4) << 4;            // A col byte offset: 0 / 16
    uint32_t a_off[4], a_xor[4];
#pragma unroll
    for (int mi = 0; mi < 4; mi++) {
        const int r = warp_m * 64 + mi * 16 + lr16;
        a_off[mi] = (uint32_t)r * 128;
        a_xor[mi] = (uint32_t)((r & 7) << 4);
    }
    const int brlo = (lane & 7) + ((lane >> 4) << 3);  // B row-in-16
    const int bhi  = ((lane >> 3) & 1) << 4;           // B col byte: 0 / 16
    uint32_t b_off[4], b_xor[4];
#pragma unroll
    for (int nj = 0; nj < 4; nj++) {
        const int r = warp_n * 64 + nj * 16 + brlo;
        b_off[nj] = (uint32_t)r * 128;
        b_xor[nj] = (uint32_t)((r & 7) << 4);
    }

    const int gid = lane >> 2;
    const int qid = lane & 3;

    int slot = 0, phase = 0;   // consumer ring cursor, continuous across tiles
    int g = 0;                 // consumer global step

    for (int kt = 0; kt < nt; kt++) {
        const int t  = cta + kt * gridn;
        const int bm = (t >> 5) * BM;
        const int bn = (t & 31) * BN;

        float c[4][8][4];
#pragma unroll
        for (int i = 0; i < 4; i++)
#pragma unroll
            for (int j = 0; j < 8; j++)
#pragma unroll
                for (int k = 0; k < 4; k++) c[i][j][k] = 0.0f;

        for (int s = 0; s < KSTEPS; s++) {
            // Producer: issue global step p = g + STAGES-1 (crosses tile bounds)
            if (tid == 0) {
                const int p = g + STAGES - 1;
                if (p < total_steps) {
                    const int ps = p & (STAGES - 1);
                    if (p >= STAGES) MBAR_WAIT(mb_empty + 8 * ps, ((p >> 2) - 1) & 1);
                    const int pk = p >> 6;
                    const int pt = cta + pk * gridn;
                    const int psl = p & (KSTEPS - 1);
                    MBAR_EXPECT_TX(mb_full + 8 * ps, (uint32_t)STAGE_BYTES);
                    const uint32_t sa = tiles + ps * STAGE_BYTES;
                    TMA2D(sa,           &tmap_x, psl * BK, (pt >> 5) * BM, mb_full + 8 * ps);
                    TMA2D(sa + A_BYTES, &tmap_w, psl * BK, (pt & 31) * BN, mb_full + 8 * ps);
                }
            }

            MBAR_WAIT(mb_full + 8 * slot, phase);
            const uint32_t aT = tiles + slot * STAGE_BYTES;
            const uint32_t bT = aT + A_BYTES;

#pragma unroll
            for (int ks = 0; ks < 4; ks++) {
                uint32_t a[4][4], b[4][4];
                const uint32_t acol = (uint32_t)(ks * 32 + ahi);
                const uint32_t bcol = (uint32_t)(ks * 32 + bhi);
#pragma unroll
                for (int mi = 0; mi < 4; mi++)
                    ldsm4(a[mi], aT + a_off[mi] + (acol ^ a_xor[mi]));
#pragma unroll
                for (int nj = 0; nj < 4; nj++)
                    ldsm4(b[nj], bT + b_off[nj] + (bcol ^ b_xor[nj]));
#pragma unroll
                for (int mi = 0; mi < 4; mi++)
#pragma unroll
                    for (int nj = 0; nj < 8; nj++)
                        mma16816(c[mi][nj], a[mi], &b[nj >> 1][(nj & 1) * 2]);
            }

            if (lane == 0) MBAR_ARRIVE(mb_empty + 8 * slot);
            if (++slot == STAGES) { slot = 0; phase ^= 1; }
            g++;
        }

        // Epilogue for tile t (next tile's stages already landing in the ring)
#pragma unroll
        for (int nj = 0; nj < 8; nj++) {
            const int col = bn + warp_n * 64 + nj * 8 + qid * 2;
            const float b0 = __ldg(bias + col);
            const float b1 = __ldg(bias + col + 1);
#pragma unroll
            for (int mi = 0; mi < 4; mi++) {
                const int row = bm + warp_m * 64 + mi * 16 + gid;
                float2 v0 = make_float2(c[mi][nj][0] + b0, c[mi][nj][1] + b1);
                float2 v1 = make_float2(c[mi][nj][2] + b0, c[mi][nj][3] + b1);
                *reinterpret_cast<float2*>(out + (size_t)row * Ntot + col)       = v0;
                *reinterpret_cast<float2*>(out + (size_t)(row + 8) * Ntot + col) = v1;
            }
        }
    }
}

// ---------------------------------------------------------------------------
// Host launch
// ---------------------------------------------------------------------------
typedef CUresult (*EncodeTiledFn)(
    CUtensorMap*, CUtensorMapDataType, cuuint32_t, void*,
    const cuuint64_t*, const cuuint64_t*, const cuuint32_t*, const cuuint32_t*,
    CUtensorMapInterleave, CUtensorMapSwizzle, CUtensorMapL2promotion,
    CUtensorMapFloatOOBfill);

extern "C" void kernel_launch(void* const* d_in, const int* in_sizes, int n_in,
                              void* d_out, int out_size) {
    const float* x    = (const float*)d_in[0];  // [8192, 4096]
    const float* W    = (const float*)d_in[1];  // [4096, 4096]
    const float* bias = (const float*)d_in[2];  // [4096]
    const float* down = (const float*)d_in[3];  // [4096, 16]
    const float* up   = (const float*)d_in[4];  // [16, 4096]
    float* out = (float*)d_out;                 // [8192, 4096]
    (void)in_sizes; (void)n_in; (void)out_size;

    static EncodeTiledFn enc = nullptr;
    if (!enc) {
        void* p = nullptr;
        cudaDriverEntryPointQueryResult qr;
        cudaGetDriverEntryPointByVersion("cuTensorMapEncodeTiled", &p, 12000,
                                         cudaEnableDefault, &qr);
        enc = (EncodeTiledFn)p;
    }
    void* xh_ptr = nullptr, *wh_ptr = nullptr;
    cudaGetSymbolAddress(&xh_ptr, g_xh);
    cudaGetSymbolAddress(&wh_ptr, g_wh);

    static int nsm = 0;
    if (!nsm) {
        cudaDeviceGetAttribute(&nsm, cudaDevAttrMultiProcessorCount, 0);
        if (nsm <= 0) nsm = 148;
    }

    CUtensorMap mx, mw;
    {
        cuuint64_t dims[2]    = {(cuuint64_t)Ktot, (cuuint64_t)Mtot};
        cuuint64_t strides[1] = {(cuuint64_t)Ktot * 2};
        cuuint32_t box[2]     = {(cuuint32_t)BK, (cuuint32_t)BM};
        cuuint32_t es[2]      = {1, 1};
        enc(&mx, CU_TENSOR_MAP_DATA_TYPE_FLOAT16, 2, xh_ptr,
            dims, strides, box, es,
            CU_TENSOR_MAP_INTERLEAVE_NONE, CU_TENSOR_MAP_SWIZZLE_128B,
            CU_TENSOR_MAP_L2_PROMOTION_L2_128B, CU_TENSOR_MAP_FLOAT_OOB_FILL_NONE);

        dims[1] = (cuuint64_t)Ntot;
        box[1]  = (cuuint32_t)BN;
        enc(&mw, CU_TENSOR_MAP_DATA_TYPE_FLOAT16, 2, wh_ptr,
            dims, strides, box, es,
            CU_TENSOR_MAP_INTERLEAVE_NONE, CU_TENSOR_MAP_SWIZZLE_128B,
            CU_TENSOR_MAP_L2_PROMOTION_L2_128B, CU_TENSOR_MAP_FLOAT_OOB_FILL_NONE);
    }

    cudaFuncSetAttribute(lora_gemm_hmma,
                         cudaFuncAttributeMaxDynamicSharedMemorySize, SMEM_ALLOC);

    prep_kernel<<<WBLOCKS + XBLOCKS, 1024>>>(W, down, up, x);

    const int gemm_grid = (NTILES < nsm) ? NTILES : nsm;
    lora_gemm_hmma<<<gemm_grid, 256, SMEM_ALLOC>>>(mx, mw, bias, out);
}